// round 3
// baseline (speedup 1.0000x reference)
#include <cuda_runtime.h>
#include <cuda_bf16.h>

#define BSZ 512
#define HD 512
#define G4H 2048
#define NSTEP 256
#define NBT 4           // batch tiles (128 each)
#define NUT 32          // unit tiles (16 each)
#define NBLK (NBT*NUT)  // 128 CTAs, all co-resident on 148 SMs
#define BM 128          // batch tile
#define NU 16           // units per CTA
#define GN 64           // gate rows per CTA (16 units x 4 gates)
#define KT 16           // K chunk
#define NTH 256

// Persistent state (no allocation allowed)
__device__ float gH0[2][BSZ][HD];
__device__ float gH1[2][BSZ][HD];
__device__ float gC0[BSZ][HD];
__device__ float gC1[BSZ][HD];
__device__ unsigned gBar;

__device__ __forceinline__ float sigf(float z)      { return 1.0f / (1.0f + __expf(-z)); }
__device__ __forceinline__ float tanhfast(float z)  { return 2.0f / (1.0f + __expf(-2.0f * z)) - 1.0f; }

__device__ __forceinline__ void grid_sync(unsigned &nbar) {
    __threadfence();          // release: make this CTA's h/c writes L2-visible
    __syncthreads();
    nbar++;
    if (threadIdx.x == 0) {
        atomicAdd(&gBar, 1u);
        const unsigned target = nbar * NBLK;
        while (*((volatile unsigned*)&gBar) < target) __nanosleep(64);
    }
    __syncthreads();
}

// C[128 x 64] += A[128 x K] * W_rows^T, K stepped in 16-chunks, reg-prefetch double buffer.
// Gate-row r (0..63) maps to global weight row j = 512*(r&3) + u0 + (r>>2),
// so thread tx's 4 columns (r = 4*tx..4*tx+3) are gates i,f,g,o of unit u0+tx.
__device__ __forceinline__ void gemm_acc(
    const float* __restrict__ Aglob,   // [BSZ][HD], rows b0..b0+127 used
    const float* __restrict__ Wglob,   // [2048][512]
    int b0, int u0, int tid, int tx, int ty,
    float (*As)[132], float (*Bs)[68],
    float acc[8][4])
{
    const int arow0 = tid >> 2;        // 0..63
    const int arow1 = arow0 + 64;      // 64..127
    const int akq   = tid & 3;         // float4 slot within 16-wide chunk
    const int brow  = tid >> 2;        // 0..63
    const int bj    = ((brow & 3) * HD) + u0 + (brow >> 2);

    const float* aptr0 = Aglob + (size_t)(b0 + arow0) * HD + akq * 4;
    const float* aptr1 = Aglob + (size_t)(b0 + arow1) * HD + akq * 4;
    const float* bptr  = Wglob + (size_t)bj * HD + akq * 4;

    float4 ra0 = __ldcg((const float4*)aptr0);
    float4 ra1 = __ldcg((const float4*)aptr1);
    float4 rb  = *(const float4*)bptr;

    #pragma unroll 1
    for (int kc = 0; kc < HD / KT; ++kc) {
        __syncthreads();   // previous chunk's compute finished
        As[akq*4+0][arow0] = ra0.x; As[akq*4+1][arow0] = ra0.y;
        As[akq*4+2][arow0] = ra0.z; As[akq*4+3][arow0] = ra0.w;
        As[akq*4+0][arow1] = ra1.x; As[akq*4+1][arow1] = ra1.y;
        As[akq*4+2][arow1] = ra1.z; As[akq*4+3][arow1] = ra1.w;
        Bs[akq*4+0][brow] = rb.x;   Bs[akq*4+1][brow] = rb.y;
        Bs[akq*4+2][brow] = rb.z;   Bs[akq*4+3][brow] = rb.w;
        __syncthreads();

        if (kc + 1 < HD / KT) {    // prefetch next chunk under the compute
            ra0 = __ldcg((const float4*)(aptr0 + (kc + 1) * KT));
            ra1 = __ldcg((const float4*)(aptr1 + (kc + 1) * KT));
            rb  = *(const float4*)(bptr  + (kc + 1) * KT);
        }

        #pragma unroll
        for (int kk = 0; kk < KT; ++kk) {
            float4 alo = *(const float4*)&As[kk][ty * 8];
            float4 ahi = *(const float4*)&As[kk][ty * 8 + 4];
            float4 bb  = *(const float4*)&Bs[kk][tx * 4];
            float a[8] = {alo.x, alo.y, alo.z, alo.w, ahi.x, ahi.y, ahi.z, ahi.w};
            float bv[4] = {bb.x, bb.y, bb.z, bb.w};
            #pragma unroll
            for (int m = 0; m < 8; ++m)
                #pragma unroll
                for (int n = 0; n < 4; ++n)
                    acc[m][n] += a[m] * bv[n];
        }
    }
}

__global__ void init_kernel(const float* __restrict__ h, const float* __restrict__ c) {
    if (blockIdx.x == 0 && threadIdx.x == 0) gBar = 0u;
    const int n = BSZ * HD;
    for (int i = blockIdx.x * blockDim.x + threadIdx.x; i < n; i += gridDim.x * blockDim.x) {
        ((float*)gH0)[i] = h[i];          // layer 0 h -> ping buffer 0
        ((float*)gH1)[i] = h[n + i];      // layer 1 h
        ((float*)gC0)[i] = c[i];
        ((float*)gC1)[i] = c[n + i];
    }
}

__global__ void __launch_bounds__(NTH, 1) lstm_kernel(
    const float* __restrict__ W_ih0, const float* __restrict__ W_hh0,
    const float* __restrict__ b_ih0, const float* __restrict__ b_hh0,
    const float* __restrict__ W_ih1, const float* __restrict__ W_hh1,
    const float* __restrict__ b_ih1, const float* __restrict__ b_hh1,
    const float* __restrict__ fc_w,  const float* __restrict__ fc_b,
    float* __restrict__ out)
{
    __shared__ __align__(16) float As[KT][132];
    __shared__ __align__(16) float Bs[KT][68];
    __shared__ float sx[BM];
    __shared__ float sred[NTH];
    __shared__ float sfcw[HD];
    __shared__ float sbias0[GN], swih0[GN], sbias1[GN];

    const int tid = threadIdx.x;
    const int tx  = tid & 15;         // unit within tile (4 gate cols)
    const int ty  = tid >> 4;         // batch group (8 batches)
    const int bt  = blockIdx.x >> 5;  // 0..3
    const int ut  = blockIdx.x & 31;  // 0..31
    const int b0  = bt * BM;
    const int u0  = ut * NU;
    const float fcb = fc_b[0];

    for (int i = tid; i < HD; i += NTH) sfcw[i] = fc_w[i];
    if (tid < GN) {
        const int lu = tid >> 2, g = tid & 3;
        const int j = g * HD + u0 + lu;
        sbias0[tid] = b_ih0[j] + b_hh0[j];
        swih0[tid]  = W_ih0[j];
        sbias1[tid] = b_ih1[j] + b_hh1[j];
    }
    __syncthreads();

    unsigned nbar = 0;

    for (int t = 0; t < NSTEP; ++t) {
        const int rp = t & 1, wp = rp ^ 1;

        // ---- Phase A: x_t = fc(h1) (redundant per CTA, deterministic), then layer-0 GEMM+update
        if (t == 0) {
            if (tid < BM) sx[tid] = 0.0f;
        } else {
            const int bl = tid & 127;
            const int half = tid >> 7;
            const float* hrow = &gH1[rp][b0 + bl][half * 256];
            const float* wrow = &sfcw[half * 256];
            float p = 0.0f;
            #pragma unroll 8
            for (int k = 0; k < 256; k += 4) {
                float4 hv = __ldcg((const float4*)(hrow + k));
                p += hv.x * wrow[k] + hv.y * wrow[k+1] + hv.z * wrow[k+2] + hv.w * wrow[k+3];
            }
            sred[tid] = p;
            __syncthreads();
            if (tid < BM) {
                const float x = sred[tid] + sred[tid + 128] + fcb;
                sx[tid] = x;
                if (ut == 0) out[(size_t)(b0 + tid) * NSTEP + (t - 1)] = x;
            }
        }

        {
            float acc[8][4];
            #pragma unroll
            for (int m = 0; m < 8; ++m)
                #pragma unroll
                for (int n = 0; n < 4; ++n) acc[m][n] = 0.0f;

            gemm_acc(&gH0[rp][0][0], W_hh0, b0, u0, tid, tx, ty, As, Bs, acc);

            const int u = u0 + tx;
            #pragma unroll
            for (int m = 0; m < 8; ++m) {
                const int b = b0 + ty * 8 + m;
                const float xb = sx[ty * 8 + m];
                const float gi = acc[m][0] + sbias0[tx*4+0] + xb * swih0[tx*4+0];
                const float gf = acc[m][1] + sbias0[tx*4+1] + xb * swih0[tx*4+1];
                const float gg = acc[m][2] + sbias0[tx*4+2] + xb * swih0[tx*4+2];
                const float go = acc[m][3] + sbias0[tx*4+3] + xb * swih0[tx*4+3];
                const float cold = gC0[b][u];
                const float cn = sigf(gf) * cold + sigf(gi) * tanhfast(gg);
                gC0[b][u] = cn;
                gH0[wp][b][u] = sigf(go) * tanhfast(cn);
            }
        }
        grid_sync(nbar);

        // ---- Phase B: layer-1 GEMM (K=1024: h0_new then h1_old) + update
        {
            float acc[8][4];
            #pragma unroll
            for (int m = 0; m < 8; ++m)
                #pragma unroll
                for (int n = 0; n < 4; ++n) acc[m][n] = 0.0f;

            gemm_acc(&gH0[wp][0][0], W_ih1, b0, u0, tid, tx, ty, As, Bs, acc);
            gemm_acc(&gH1[rp][0][0], W_hh1, b0, u0, tid, tx, ty, As, Bs, acc);

            const int u = u0 + tx;
            #pragma unroll
            for (int m = 0; m < 8; ++m) {
                const int b = b0 + ty * 8 + m;
                const float gi = acc[m][0] + sbias1[tx*4+0];
                const float gf = acc[m][1] + sbias1[tx*4+1];
                const float gg = acc[m][2] + sbias1[tx*4+2];
                const float go = acc[m][3] + sbias1[tx*4+3];
                const float cold = gC1[b][u];
                const float cn = sigf(gf) * cold + sigf(gi) * tanhfast(gg);
                gC1[b][u] = cn;
                gH1[wp][b][u] = sigf(go) * tanhfast(cn);
            }
        }
        grid_sync(nbar);
    }

    // ---- Final prediction t=255 from gH1[0] (step 255 wrote buffer 0)
    if (ut == 0) {
        const int bl = tid & 127;
        const int half = tid >> 7;
        const float* hrow = &gH1[0][b0 + bl][half * 256];
        const float* wrow = &sfcw[half * 256];
        float p = 0.0f;
        #pragma unroll 8
        for (int k = 0; k < 256; k += 4) {
            float4 hv = __ldcg((const float4*)(hrow + k));
            p += hv.x * wrow[k] + hv.y * wrow[k+1] + hv.z * wrow[k+2] + hv.w * wrow[k+3];
        }
        sred[tid] = p;
        __syncthreads();
        if (tid < BM)
            out[(size_t)(b0 + tid) * NSTEP + 255] = sred[tid] + sred[tid + 128] + fcb;
    }
}

extern "C" void kernel_launch(void* const* d_in, const int* in_sizes, int n_in,
                              void* d_out, int out_size)
{
    const float* h     = (const float*)d_in[0];
    const float* c     = (const float*)d_in[1];
    const float* W_ih0 = (const float*)d_in[2];
    const float* W_hh0 = (const float*)d_in[3];
    const float* b_ih0 = (const float*)d_in[4];
    const float* b_hh0 = (const float*)d_in[5];
    const float* W_ih1 = (const float*)d_in[6];
    const float* W_hh1 = (const float*)d_in[7];
    const float* b_ih1 = (const float*)d_in[8];
    const float* b_hh1 = (const float*)d_in[9];
    const float* fc_w  = (const float*)d_in[10];
    const float* fc_b  = (const float*)d_in[11];

    init_kernel<<<256, 256>>>(h, c);
    lstm_kernel<<<NBLK, NTH>>>(W_ih0, W_hh0, b_ih0, b_hh0,
                               W_ih1, W_hh1, b_ih1, b_hh1,
                               fc_w, fc_b, (float*)d_out);
}

// round 4
// speedup vs baseline: 1.0008x; 1.0008x over previous
#include <cuda_runtime.h>
#include <cuda_bf16.h>

#define BSZ 512
#define HD 512
#define G4H 2048
#define NSTEP 256
#define NBT 4           // batch tiles (128 each)
#define NUT 32          // unit tiles (16 each)
#define NBLK (NBT*NUT)  // 128 CTAs, all co-resident on 148 SMs
#define BM 128          // batch tile
#define NU 16           // units per CTA
#define GN 64           // gate rows per CTA (16 units x 4 gates)
#define KT 16           // K chunk
#define NTH 256

// Persistent state (no allocation allowed)
__device__ float gH0[2][BSZ][HD];
__device__ float gH1[2][BSZ][HD];
__device__ float gC0[BSZ][HD];
__device__ float gC1[BSZ][HD];
__device__ unsigned gBar;

__device__ __forceinline__ float sigf(float z)      { return 1.0f / (1.0f + __expf(-z)); }
__device__ __forceinline__ float tanhfast(float z)  { return 2.0f / (1.0f + __expf(-2.0f * z)) - 1.0f; }

__device__ __forceinline__ void grid_sync(unsigned &nbar) {
    __threadfence();          // release: make this CTA's h/c writes L2-visible
    __syncthreads();
    nbar++;
    if (threadIdx.x == 0) {
        atomicAdd(&gBar, 1u);
        const unsigned target = nbar * NBLK;
        while (*((volatile unsigned*)&gBar) < target) __nanosleep(64);
    }
    __syncthreads();
}

// C[128 x 64] += A[128 x K] * W_rows^T, K stepped in 16-chunks, reg-prefetch double buffer.
// Gate-row r (0..63) maps to global weight row j = 512*(r&3) + u0 + (r>>2),
// so thread tx's 4 columns (r = 4*tx..4*tx+3) are gates i,f,g,o of unit u0+tx.
__device__ __forceinline__ void gemm_acc(
    const float* __restrict__ Aglob,   // [BSZ][HD], rows b0..b0+127 used
    const float* __restrict__ Wglob,   // [2048][512]
    int b0, int u0, int tid, int tx, int ty,
    float (*As)[132], float (*Bs)[68],
    float acc[8][4])
{
    const int arow0 = tid >> 2;        // 0..63
    const int arow1 = arow0 + 64;      // 64..127
    const int akq   = tid & 3;         // float4 slot within 16-wide chunk
    const int brow  = tid >> 2;        // 0..63
    const int bj    = ((brow & 3) * HD) + u0 + (brow >> 2);

    const float* aptr0 = Aglob + (size_t)(b0 + arow0) * HD + akq * 4;
    const float* aptr1 = Aglob + (size_t)(b0 + arow1) * HD + akq * 4;
    const float* bptr  = Wglob + (size_t)bj * HD + akq * 4;

    float4 ra0 = __ldcg((const float4*)aptr0);
    float4 ra1 = __ldcg((const float4*)aptr1);
    float4 rb  = *(const float4*)bptr;

    #pragma unroll 1
    for (int kc = 0; kc < HD / KT; ++kc) {
        __syncthreads();   // previous chunk's compute finished
        As[akq*4+0][arow0] = ra0.x; As[akq*4+1][arow0] = ra0.y;
        As[akq*4+2][arow0] = ra0.z; As[akq*4+3][arow0] = ra0.w;
        As[akq*4+0][arow1] = ra1.x; As[akq*4+1][arow1] = ra1.y;
        As[akq*4+2][arow1] = ra1.z; As[akq*4+3][arow1] = ra1.w;
        Bs[akq*4+0][brow] = rb.x;   Bs[akq*4+1][brow] = rb.y;
        Bs[akq*4+2][brow] = rb.z;   Bs[akq*4+3][brow] = rb.w;
        __syncthreads();

        if (kc + 1 < HD / KT) {    // prefetch next chunk under the compute
            ra0 = __ldcg((const float4*)(aptr0 + (kc + 1) * KT));
            ra1 = __ldcg((const float4*)(aptr1 + (kc + 1) * KT));
            rb  = *(const float4*)(bptr  + (kc + 1) * KT);
        }

        #pragma unroll
        for (int kk = 0; kk < KT; ++kk) {
            float4 alo = *(const float4*)&As[kk][ty * 8];
            float4 ahi = *(const float4*)&As[kk][ty * 8 + 4];
            float4 bb  = *(const float4*)&Bs[kk][tx * 4];
            float a[8] = {alo.x, alo.y, alo.z, alo.w, ahi.x, ahi.y, ahi.z, ahi.w};
            float bv[4] = {bb.x, bb.y, bb.z, bb.w};
            #pragma unroll
            for (int m = 0; m < 8; ++m)
                #pragma unroll
                for (int n = 0; n < 4; ++n)
                    acc[m][n] += a[m] * bv[n];
        }
    }
}

__global__ void init_kernel(const float* __restrict__ h, const float* __restrict__ c) {
    if (blockIdx.x == 0 && threadIdx.x == 0) gBar = 0u;
    const int n = BSZ * HD;
    for (int i = blockIdx.x * blockDim.x + threadIdx.x; i < n; i += gridDim.x * blockDim.x) {
        ((float*)gH0)[i] = h[i];          // layer 0 h -> ping buffer 0
        ((float*)gH1)[i] = h[n + i];      // layer 1 h
        ((float*)gC0)[i] = c[i];
        ((float*)gC1)[i] = c[n + i];
    }
}

__global__ void __launch_bounds__(NTH, 1) lstm_kernel(
    const float* __restrict__ W_ih0, const float* __restrict__ W_hh0,
    const float* __restrict__ b_ih0, const float* __restrict__ b_hh0,
    const float* __restrict__ W_ih1, const float* __restrict__ W_hh1,
    const float* __restrict__ b_ih1, const float* __restrict__ b_hh1,
    const float* __restrict__ fc_w,  const float* __restrict__ fc_b,
    float* __restrict__ out)
{
    __shared__ __align__(16) float As[KT][132];
    __shared__ __align__(16) float Bs[KT][68];
    __shared__ float sx[BM];
    __shared__ float sred[NTH];
    __shared__ float sfcw[HD];
    __shared__ float sbias0[GN], swih0[GN], sbias1[GN];

    const int tid = threadIdx.x;
    const int tx  = tid & 15;         // unit within tile (4 gate cols)
    const int ty  = tid >> 4;         // batch group (8 batches)
    const int bt  = blockIdx.x >> 5;  // 0..3
    const int ut  = blockIdx.x & 31;  // 0..31
    const int b0  = bt * BM;
    const int u0  = ut * NU;
    const float fcb = fc_b[0];

    for (int i = tid; i < HD; i += NTH) sfcw[i] = fc_w[i];
    if (tid < GN) {
        const int lu = tid >> 2, g = tid & 3;
        const int j = g * HD + u0 + lu;
        sbias0[tid] = b_ih0[j] + b_hh0[j];
        swih0[tid]  = W_ih0[j];
        sbias1[tid] = b_ih1[j] + b_hh1[j];
    }
    __syncthreads();

    unsigned nbar = 0;

    for (int t = 0; t < NSTEP; ++t) {
        const int rp = t & 1, wp = rp ^ 1;

        // ---- Phase A: x_t = fc(h1) (redundant per CTA, deterministic), then layer-0 GEMM+update
        if (t == 0) {
            if (tid < BM) sx[tid] = 0.0f;
        } else {
            const int bl = tid & 127;
            const int half = tid >> 7;
            const float* hrow = &gH1[rp][b0 + bl][half * 256];
            const float* wrow = &sfcw[half * 256];
            float p = 0.0f;
            #pragma unroll 8
            for (int k = 0; k < 256; k += 4) {
                float4 hv = __ldcg((const float4*)(hrow + k));
                p += hv.x * wrow[k] + hv.y * wrow[k+1] + hv.z * wrow[k+2] + hv.w * wrow[k+3];
            }
            sred[tid] = p;
            __syncthreads();
            if (tid < BM) {
                const float x = sred[tid] + sred[tid + 128] + fcb;
                sx[tid] = x;
                if (ut == 0) out[(size_t)(b0 + tid) * NSTEP + (t - 1)] = x;
            }
        }

        {
            float acc[8][4];
            #pragma unroll
            for (int m = 0; m < 8; ++m)
                #pragma unroll
                for (int n = 0; n < 4; ++n) acc[m][n] = 0.0f;

            gemm_acc(&gH0[rp][0][0], W_hh0, b0, u0, tid, tx, ty, As, Bs, acc);

            const int u = u0 + tx;
            #pragma unroll
            for (int m = 0; m < 8; ++m) {
                const int b = b0 + ty * 8 + m;
                const float xb = sx[ty * 8 + m];
                const float gi = acc[m][0] + sbias0[tx*4+0] + xb * swih0[tx*4+0];
                const float gf = acc[m][1] + sbias0[tx*4+1] + xb * swih0[tx*4+1];
                const float gg = acc[m][2] + sbias0[tx*4+2] + xb * swih0[tx*4+2];
                const float go = acc[m][3] + sbias0[tx*4+3] + xb * swih0[tx*4+3];
                const float cold = gC0[b][u];
                const float cn = sigf(gf) * cold + sigf(gi) * tanhfast(gg);
                gC0[b][u] = cn;
                gH0[wp][b][u] = sigf(go) * tanhfast(cn);
            }
        }
        grid_sync(nbar);

        // ---- Phase B: layer-1 GEMM (K=1024: h0_new then h1_old) + update
        {
            float acc[8][4];
            #pragma unroll
            for (int m = 0; m < 8; ++m)
                #pragma unroll
                for (int n = 0; n < 4; ++n) acc[m][n] = 0.0f;

            gemm_acc(&gH0[wp][0][0], W_ih1, b0, u0, tid, tx, ty, As, Bs, acc);
            gemm_acc(&gH1[rp][0][0], W_hh1, b0, u0, tid, tx, ty, As, Bs, acc);

            const int u = u0 + tx;
            #pragma unroll
            for (int m = 0; m < 8; ++m) {
                const int b = b0 + ty * 8 + m;
                const float gi = acc[m][0] + sbias1[tx*4+0];
                const float gf = acc[m][1] + sbias1[tx*4+1];
                const float gg = acc[m][2] + sbias1[tx*4+2];
                const float go = acc[m][3] + sbias1[tx*4+3];
                const float cold = gC1[b][u];
                const float cn = sigf(gf) * cold + sigf(gi) * tanhfast(gg);
                gC1[b][u] = cn;
                gH1[wp][b][u] = sigf(go) * tanhfast(cn);
            }
        }
        grid_sync(nbar);
    }

    // ---- Final prediction t=255 from gH1[0] (step 255 wrote buffer 0)
    if (ut == 0) {
        const int bl = tid & 127;
        const int half = tid >> 7;
        const float* hrow = &gH1[0][b0 + bl][half * 256];
        const float* wrow = &sfcw[half * 256];
        float p = 0.0f;
        #pragma unroll 8
        for (int k = 0; k < 256; k += 4) {
            float4 hv = __ldcg((const float4*)(hrow + k));
            p += hv.x * wrow[k] + hv.y * wrow[k+1] + hv.z * wrow[k+2] + hv.w * wrow[k+3];
        }
        sred[tid] = p;
        __syncthreads();
        if (tid < BM)
            out[(size_t)(b0 + tid) * NSTEP + 255] = sred[tid] + sred[tid + 128] + fcb;
    }
}

extern "C" void kernel_launch(void* const* d_in, const int* in_sizes, int n_in,
                              void* d_out, int out_size)
{
    const float* h     = (const float*)d_in[0];
    const float* c     = (const float*)d_in[1];
    const float* W_ih0 = (const float*)d_in[2];
    const float* W_hh0 = (const float*)d_in[3];
    const float* b_ih0 = (const float*)d_in[4];
    const float* b_hh0 = (const float*)d_in[5];
    const float* W_ih1 = (const float*)d_in[6];
    const float* W_hh1 = (const float*)d_in[7];
    const float* b_ih1 = (const float*)d_in[8];
    const float* b_hh1 = (const float*)d_in[9];
    const float* fc_w  = (const float*)d_in[10];
    const float* fc_b  = (const float*)d_in[11];

    init_kernel<<<256, 256>>>(h, c);
    lstm_kernel<<<NBLK, NTH>>>(W_ih0, W_hh0, b_ih0, b_hh0,
                               W_ih1, W_hh1, b_ih1, b_hh1,
                               fc_w, fc_b, (float*)d_out);
}

// round 6
// speedup vs baseline: 1.7185x; 1.7171x over previous
#include <cuda_runtime.h>
#include <cuda_bf16.h>
#include <cstdint>

#define BSZ 512
#define HD 512
#define NSTEP 256
#define NUT 32
#define NBLK 128
#define BM 128
#define NTH 256
// smem buffer layout (bytes), pitch 144B per 64-elem bf16 row
#define OFF_AH 0
#define OFF_AL 18432
#define OFF_BH 36864
#define OFF_BL 46080
#define BUFB   55296
#define SMEM_DYN (2*BUFB)

// ---------------- persistent device state ----------------
__device__ __align__(16) __nv_bfloat16 gH0h[2][BSZ][HD];
__device__ __align__(16) __nv_bfloat16 gH0l[2][BSZ][HD];
__device__ __align__(16) __nv_bfloat16 gH1h[2][BSZ][HD];
__device__ __align__(16) __nv_bfloat16 gH1l[2][BSZ][HD];
__device__ __align__(16) float gC0[BSZ][HD];
__device__ __align__(16) float gC1[BSZ][HD];
__device__ float gXpart[NUT][BSZ];
__device__ unsigned gBar;
// weights: 24 chunks x 32 u-tiles x {hi,lo} x (64 gate-rows x 64 k) bf16, k-contiguous
__device__ __align__(16) __nv_bfloat16 gWT[24][NUT][2][64*64];

// ---------------- helpers ----------------
__device__ __forceinline__ float sigf(float z)     { return 1.0f / (1.0f + __expf(-z)); }
__device__ __forceinline__ float tanhfast(float z) { return 2.0f / (1.0f + __expf(-2.0f * z)) - 1.0f; }

__device__ __forceinline__ uint32_t smem_u32(const void* p) {
    uint32_t a;
    asm("{ .reg .u64 t; cvta.to.shared.u64 t, %1; cvt.u32.u64 %0, t; }" : "=r"(a) : "l"(p));
    return a;
}
__device__ __forceinline__ void cpa16(uint32_t d, const void* s) {
    asm volatile("cp.async.cg.shared.global [%0], [%1], 16;"
                 :: "r"(d), "l"(__cvta_generic_to_global(s)) : "memory");
}
#define CP_COMMIT() asm volatile("cp.async.commit_group;" ::: "memory")

#define LDX4(r, a) \
    asm volatile("ldmatrix.sync.aligned.m8n8.x4.shared.b16 {%0,%1,%2,%3}, [%4];" \
        : "=r"((r)[0]), "=r"((r)[1]), "=r"((r)[2]), "=r"((r)[3]) : "r"(a))

#define MMA(d, a, b) \
    asm volatile("mma.sync.aligned.m16n8k16.row.col.f32.bf16.bf16.f32 " \
        "{%0,%1,%2,%3}, {%4,%5,%6,%7}, {%8,%9}, {%0,%1,%2,%3};" \
        : "+f"((d)[0]), "+f"((d)[1]), "+f"((d)[2]), "+f"((d)[3]) \
        : "r"((a)[0]), "r"((a)[1]), "r"((a)[2]), "r"((a)[3]), "r"((b)[0]), "r"((b)[1]))

__device__ __forceinline__ void grid_sync(unsigned &nbar) {
    __threadfence();
    __syncthreads();
    nbar++;
    if (threadIdx.x == 0) {
        atomicAdd(&gBar, 1u);
        const unsigned target = nbar * NBLK;
        while (*((volatile unsigned*)&gBar) < target) __nanosleep(64);
    }
    __syncthreads();
}

// ---------------- init: states + weight split ----------------
__global__ void init_kernel(const float* __restrict__ h, const float* __restrict__ c,
                            const float* __restrict__ W_hh0, const float* __restrict__ W_ih1,
                            const float* __restrict__ W_hh1)
{
    const int gtid = blockIdx.x * blockDim.x + threadIdx.x;
    const int gsz  = gridDim.x * blockDim.x;
    if (gtid == 0) gBar = 0u;

    const int n = BSZ * HD;
    for (int i = gtid; i < n; i += gsz) {
        float v0 = h[i], v1 = h[n + i];
        __nv_bfloat16 a0 = __float2bfloat16(v0);
        __nv_bfloat16 a1 = __float2bfloat16(v1);
        (&gH0h[0][0][0])[i] = a0;
        (&gH0l[0][0][0])[i] = __float2bfloat16(v0 - __bfloat162float(a0));
        (&gH1h[0][0][0])[i] = a1;
        (&gH1l[0][0][0])[i] = __float2bfloat16(v1 - __bfloat162float(a1));
        (&gC0[0][0])[i] = c[i];
        (&gC1[0][0])[i] = c[n + i];
    }

    const long WN = 24L * NUT * 64 * 64;
    for (long idx = gtid; idx < WN; idx += gsz) {
        const int kk   = (int)(idx & 63);
        const int nrow = (int)((idx >> 6) & 63);
        const int ut   = (int)((idx >> 12) & 31);
        const int ch   = (int)(idx >> 17);
        const float* W = (ch < 8) ? W_hh0 : ((ch < 16) ? W_ih1 : W_hh1);
        // gate-row r -> weight row j: gate = r&3, unit = r>>2
        const int j = (nrow & 3) * HD + ut * 16 + (nrow >> 2);
        const float v = W[(size_t)j * HD + (ch & 7) * 64 + kk];
        __nv_bfloat16 hi = __float2bfloat16(v);
        __nv_bfloat16 lo = __float2bfloat16(v - __bfloat162float(hi));
        gWT[ch][ut][0][nrow * 64 + kk] = hi;
        gWT[ch][ut][1][nrow * 64 + kk] = lo;
    }
}

// ---------------- main persistent kernel ----------------
__global__ void __launch_bounds__(NTH, 1) lstm_tc_kernel(
    const float* __restrict__ W_ih0,
    const float* __restrict__ b_ih0, const float* __restrict__ b_hh0,
    const float* __restrict__ b_ih1, const float* __restrict__ b_hh1,
    const float* __restrict__ fc_w,  const float* __restrict__ fc_b,
    float* __restrict__ out)
{
    extern __shared__ unsigned char sbuf[];

    __shared__ float sx[BM];
    __shared__ float sp[2][BM];
    __shared__ float sbias0[64], swih0[64], sbias1[64], sfcw16[16];

    const int tid = threadIdx.x;
    const int lid = tid & 31;
    const int wid = tid >> 5;
    const int wm  = wid & 3;          // M tile: rows wm*32..+31
    const int wn  = wid >> 2;         // N tile: gate-rows wn*32..+31
    const int bt  = blockIdx.x >> 5;
    const int ut  = blockIdx.x & 31;
    const int b0  = bt * BM;
    const int u0  = ut * 16;
    const float fcb = fc_b[0];
    const uint32_t sb32 = smem_u32(sbuf);

    if (tid < 64) {
        const int lu = tid >> 2, g = tid & 3;
        const int j = g * HD + u0 + lu;
        sbias0[tid] = b_ih0[j] + b_hh0[j];
        swih0[tid]  = W_ih0[j];
        sbias1[tid] = b_ih1[j] + b_hh1[j];
    }
    if (tid < 16) sfcw16[tid] = fc_w[u0 + tid];
    __syncthreads();

    float acc[2][4][4];
    unsigned nbar = 0;

    // ---- stage chunk c into buffer bufsel (A: split h; B: pre-split weights)
    auto stage = [&](int c, int bufsel, int rp, int wp) {
        const __nv_bfloat16 *Ah, *Al; int k0;
        if (c < 8)       { Ah = &gH0h[rp][0][0]; Al = &gH0l[rp][0][0]; k0 = c * 64; }
        else if (c < 16) { Ah = &gH0h[wp][0][0]; Al = &gH0l[wp][0][0]; k0 = (c - 8) * 64; }
        else             { Ah = &gH1h[rp][0][0]; Al = &gH1l[rp][0][0]; k0 = (c - 16) * 64; }
        const uint32_t bb = sb32 + bufsel * BUFB;
        #pragma unroll
        for (int i = 0; i < 4; ++i) {
            const int s = tid + i * NTH;          // 1024 segs: 128 rows x 8
            const int row = s >> 3, seg = s & 7;
            const uint32_t d = bb + row * 144 + seg * 16;
            const size_t so = (size_t)(b0 + row) * HD + k0 + seg * 8;
            cpa16(d + OFF_AH, Ah + so);
            cpa16(d + OFF_AL, Al + so);
        }
        #pragma unroll
        for (int i = 0; i < 2; ++i) {
            const int s = tid + i * NTH;          // 512 segs: 64 rows x 8
            const int row = s >> 3, seg = s & 7;
            const uint32_t d = bb + OFF_BH + row * 144 + seg * 16;
            const int eo = row * 64 + seg * 8;
            cpa16(d,                     &gWT[c][ut][0][eo]);
            cpa16(d + (OFF_BL - OFF_BH), &gWT[c][ut][1][eo]);
        }
        CP_COMMIT();
    };

    // ---- compute one K=64 chunk from buffer bufsel into acc
    auto compute = [&](int bufsel) {
        const uint32_t bb = sb32 + bufsel * BUFB;
        const uint32_t aoff = (wm * 32 + (lid & 15)) * 144 + (lid >> 4) * 16;
        const uint32_t boff = (wn * 32 + (lid & 15)) * 144 + (lid >> 4) * 16;
        #pragma unroll
        for (int ks = 0; ks < 4; ++ks) {
            const uint32_t ko = ks * 32;
            uint32_t Af[2][2][4];   // [split][mt][4]
            uint32_t Bf[2][4][2];   // [split][nt][2]
            #pragma unroll
            for (int mt = 0; mt < 2; ++mt) {
                LDX4(Af[0][mt], bb + OFF_AH + aoff + mt * (16 * 144) + ko);
                LDX4(Af[1][mt], bb + OFF_AL + aoff + mt * (16 * 144) + ko);
            }
            #pragma unroll
            for (int pr = 0; pr < 2; ++pr) {
                uint32_t t0[4], t1[4];
                LDX4(t0, bb + OFF_BH + boff + pr * (16 * 144) + ko);
                LDX4(t1, bb + OFF_BL + boff + pr * (16 * 144) + ko);
                Bf[0][pr*2  ][0] = t0[0]; Bf[0][pr*2  ][1] = t0[2];
                Bf[0][pr*2+1][0] = t0[1]; Bf[0][pr*2+1][1] = t0[3];
                Bf[1][pr*2  ][0] = t1[0]; Bf[1][pr*2  ][1] = t1[2];
                Bf[1][pr*2+1][0] = t1[1]; Bf[1][pr*2+1][1] = t1[3];
            }
            #pragma unroll
            for (int mt = 0; mt < 2; ++mt)
                #pragma unroll
                for (int nt = 0; nt < 4; ++nt) {
                    MMA(acc[mt][nt], Af[0][mt], Bf[0][nt]);   // hi*hi
                    MMA(acc[mt][nt], Af[0][mt], Bf[1][nt]);   // hi*lo
                    MMA(acc[mt][nt], Af[1][mt], Bf[0][nt]);   // lo*hi
                }
        }
    };

    // ---- run chunks [ca,cb] with 2-deep cp.async pipeline
    auto run_layer = [&](int ca, int cb, int rp, int wp) {
        #pragma unroll
        for (int mt = 0; mt < 2; ++mt)
            #pragma unroll
            for (int nt = 0; nt < 4; ++nt)
                #pragma unroll
                for (int q = 0; q < 4; ++q) acc[mt][nt][q] = 0.0f;
        stage(ca, 0, rp, wp);
        int buf = 0;
        #pragma unroll 1
        for (int c = ca; c <= cb; ++c) {
            if (c < cb) {
                stage(c + 1, buf ^ 1, rp, wp);
                asm volatile("cp.async.wait_group 1;" ::: "memory");
            } else {
                asm volatile("cp.async.wait_group 0;" ::: "memory");
            }
            __syncthreads();
            compute(buf);
            __syncthreads();
            buf ^= 1;
        }
    };

    // ---- fused LSTM epilogue from register accumulators
    const int mbase = wm * 32 + (lid >> 2) + ((lid & 1) ? 8 : 0);
    const int lusub = wn * 8 + ((lid & 3) >> 1);

    auto epilogue = [&](bool L1, const float* sbias, float* Cbase,
                        __nv_bfloat16* Hhb, __nv_bfloat16* Hlb) {
        #pragma unroll
        for (int mt = 0; mt < 2; ++mt) {
            const int bl = mbase + mt * 16;
            const float xb = L1 ? 0.0f : sx[bl];
            float pb = 0.0f;
            #pragma unroll
            for (int nt = 0; nt < 4; ++nt) {
                float* d = acc[mt][nt];
                const float e0 = __shfl_xor_sync(0xFFFFFFFFu, d[0], 1);
                const float e1 = __shfl_xor_sync(0xFFFFFFFFu, d[1], 1);
                const float e2 = __shfl_xor_sync(0xFFFFFFFFu, d[2], 1);
                const float e3 = __shfl_xor_sync(0xFFFFFFFFu, d[3], 1);
                float gi, gf, gg, go;
                if (!(lid & 1)) { gi = d[0]; gf = d[1]; gg = e0; go = e1; }
                else            { gi = e2;  gf = e3;  gg = d[2]; go = d[3]; }
                const int lun = lusub + nt * 2;
                gi += sbias[4*lun+0]; gf += sbias[4*lun+1];
                gg += sbias[4*lun+2]; go += sbias[4*lun+3];
                if (!L1) {
                    gi += xb * swih0[4*lun+0]; gf += xb * swih0[4*lun+1];
                    gg += xb * swih0[4*lun+2]; go += xb * swih0[4*lun+3];
                }
                const size_t off = (size_t)(b0 + bl) * HD + u0 + lun;
                const float cold = Cbase[off];
                const float cn = sigf(gf) * cold + sigf(gi) * tanhfast(gg);
                const float hn = sigf(go) * tanhfast(cn);
                Cbase[off] = cn;
                const __nv_bfloat16 hh = __float2bfloat16(hn);
                Hhb[off] = hh;
                Hlb[off] = __float2bfloat16(hn - __bfloat162float(hh));
                if (L1) pb += hn * sfcw16[lun];
            }
            if (L1) {
                pb += __shfl_xor_sync(0xFFFFFFFFu, pb, 2);
                if (!(lid & 2)) sp[wn][bl] = pb;
            }
        }
    };

    #pragma unroll 1
    for (int t = 0; t < NSTEP; ++t) {
        const int rp = t & 1, wp = rp ^ 1;

        // ---- x_t from distributed fc partials
        if (t == 0) {
            if (tid < BM) sx[tid] = 0.0f;
        } else if (tid < BM) {
            float x = fcb;
            #pragma unroll
            for (int j = 0; j < NUT; ++j) x += __ldcg(&gXpart[j][b0 + tid]);
            sx[tid] = x;
            if (ut == 0) out[(size_t)(b0 + tid) * NSTEP + (t - 1)] = x;
        }

        // ---- layer 0: K=512 (chunks 0..7), fused update
        run_layer(0, 7, rp, wp);
        epilogue(false, sbias0, &gC0[0][0], &gH0h[wp][0][0], &gH0l[wp][0][0]);
        grid_sync(nbar);

        // ---- layer 1: K=1024 (chunks 8..23), fused update + fc partial
        run_layer(8, 23, rp, wp);
        epilogue(true, sbias1, &gC1[0][0], &gH1h[wp][0][0], &gH1l[wp][0][0]);
        __syncthreads();
        if (tid < BM) gXpart[ut][b0 + tid] = sp[0][tid] + sp[1][tid];
        grid_sync(nbar);
    }

    // ---- final prediction column 255
    if (ut == 0 && tid < BM) {
        float x = fcb;
        #pragma unroll
        for (int j = 0; j < NUT; ++j) x += __ldcg(&gXpart[j][b0 + tid]);
        out[(size_t)(b0 + tid) * NSTEP + 255] = x;
    }
}

extern "C" void kernel_launch(void* const* d_in, const int* in_sizes, int n_in,
                              void* d_out, int out_size)
{
    const float* h     = (const float*)d_in[0];
    const float* c     = (const float*)d_in[1];
    const float* W_ih0 = (const float*)d_in[2];
    const float* W_hh0 = (const float*)d_in[3];
    const float* b_ih0 = (const float*)d_in[4];
    const float* b_hh0 = (const float*)d_in[5];
    const float* W_ih1 = (const float*)d_in[6];
    const float* W_hh1 = (const float*)d_in[7];
    const float* b_ih1 = (const float*)d_in[8];
    const float* b_hh1 = (const float*)d_in[9];
    const float* fc_w  = (const float*)d_in[10];
    const float* fc_b  = (const float*)d_in[11];

    cudaFuncSetAttribute(lstm_tc_kernel, cudaFuncAttributeMaxDynamicSharedMemorySize, SMEM_DYN);

    init_kernel<<<1024, 256>>>(h, c, W_hh0, W_ih1, W_hh1);
    lstm_tc_kernel<<<NBLK, NTH, SMEM_DYN>>>(W_ih0, b_ih0, b_hh0, b_ih1, b_hh1,
                                            fc_w, fc_b, (float*)d_out);
}

// round 7
// speedup vs baseline: 1.7365x; 1.0105x over previous
#include <cuda_runtime.h>
#include <cuda_bf16.h>
#include <cstdint>

#define BSZ 512
#define HD 512
#define NSTEP 256
#define NUT 32
#define NBLK 128
#define BM 128
#define NTH 512
// smem buffer layout (bytes), pitch 144B per 64-elem bf16 row
#define OFF_AH 0
#define OFF_AL 18432
#define OFF_BH 36864
#define OFF_BL 46080
#define BUFB   55296
#define SMEM_DYN (2*BUFB)

// ---------------- persistent device state ----------------
__device__ __align__(16) __nv_bfloat16 gH0h[2][BSZ][HD];
__device__ __align__(16) __nv_bfloat16 gH0l[2][BSZ][HD];
__device__ __align__(16) __nv_bfloat16 gH1h[2][BSZ][HD];
__device__ __align__(16) __nv_bfloat16 gH1l[2][BSZ][HD];
__device__ __align__(16) float gC0[BSZ][HD];
__device__ __align__(16) float gC1[BSZ][HD];
__device__ float gXpart[NUT][BSZ];
__device__ unsigned gBar;
// weights: 24 chunks x 32 u-tiles x {hi,lo} x (64 gate-rows x 64 k) bf16, k-contiguous
__device__ __align__(16) __nv_bfloat16 gWT[24][NUT][2][64*64];

// ---------------- helpers ----------------
__device__ __forceinline__ float sigf(float z)     { return 1.0f / (1.0f + __expf(-z)); }
__device__ __forceinline__ float tanhfast(float z) { return 2.0f / (1.0f + __expf(-2.0f * z)) - 1.0f; }

__device__ __forceinline__ uint32_t smem_u32(const void* p) {
    uint32_t a;
    asm("{ .reg .u64 t; cvta.to.shared.u64 t, %1; cvt.u32.u64 %0, t; }" : "=r"(a) : "l"(p));
    return a;
}
__device__ __forceinline__ void cpa16(uint32_t d, const void* s) {
    asm volatile("cp.async.cg.shared.global [%0], [%1], 16;"
                 :: "r"(d), "l"(__cvta_generic_to_global(s)) : "memory");
}
#define CP_COMMIT() asm volatile("cp.async.commit_group;" ::: "memory")

#define LDX4(r, a) \
    asm volatile("ldmatrix.sync.aligned.m8n8.x4.shared.b16 {%0,%1,%2,%3}, [%4];" \
        : "=r"((r)[0]), "=r"((r)[1]), "=r"((r)[2]), "=r"((r)[3]) : "r"(a))

#define MMA(d, a, b) \
    asm volatile("mma.sync.aligned.m16n8k16.row.col.f32.bf16.bf16.f32 " \
        "{%0,%1,%2,%3}, {%4,%5,%6,%7}, {%8,%9}, {%0,%1,%2,%3};" \
        : "+f"((d)[0]), "+f"((d)[1]), "+f"((d)[2]), "+f"((d)[3]) \
        : "r"((a)[0]), "r"((a)[1]), "r"((a)[2]), "r"((a)[3]), "r"((b)[0]), "r"((b)[1]))

__device__ __forceinline__ void grid_sync(unsigned &nbar) {
    __threadfence();
    __syncthreads();
    nbar++;
    if (threadIdx.x == 0) {
        atomicAdd(&gBar, 1u);
        const unsigned target = nbar * NBLK;
        while (*((volatile unsigned*)&gBar) < target) __nanosleep(64);
    }
    __syncthreads();
}

// ---------------- init: states + weight split ----------------
__global__ void init_kernel(const float* __restrict__ h, const float* __restrict__ c,
                            const float* __restrict__ W_hh0, const float* __restrict__ W_ih1,
                            const float* __restrict__ W_hh1)
{
    const int gtid = blockIdx.x * blockDim.x + threadIdx.x;
    const int gsz  = gridDim.x * blockDim.x;
    if (gtid == 0) gBar = 0u;

    const int n = BSZ * HD;
    for (int i = gtid; i < n; i += gsz) {
        float v0 = h[i], v1 = h[n + i];
        __nv_bfloat16 a0 = __float2bfloat16(v0);
        __nv_bfloat16 a1 = __float2bfloat16(v1);
        (&gH0h[0][0][0])[i] = a0;
        (&gH0l[0][0][0])[i] = __float2bfloat16(v0 - __bfloat162float(a0));
        (&gH1h[0][0][0])[i] = a1;
        (&gH1l[0][0][0])[i] = __float2bfloat16(v1 - __bfloat162float(a1));
        (&gC0[0][0])[i] = c[i];
        (&gC1[0][0])[i] = c[n + i];
    }

    const long WN = 24L * NUT * 64 * 64;
    for (long idx = gtid; idx < WN; idx += gsz) {
        const int kk   = (int)(idx & 63);
        const int nrow = (int)((idx >> 6) & 63);
        const int ut   = (int)((idx >> 12) & 31);
        const int ch   = (int)(idx >> 17);
        const float* W = (ch < 8) ? W_hh0 : ((ch < 16) ? W_ih1 : W_hh1);
        // gate-row r -> weight row j: gate = r&3, unit = r>>2
        const int j = (nrow & 3) * HD + ut * 16 + (nrow >> 2);
        const float v = W[(size_t)j * HD + (ch & 7) * 64 + kk];
        __nv_bfloat16 hi = __float2bfloat16(v);
        __nv_bfloat16 lo = __float2bfloat16(v - __bfloat162float(hi));
        gWT[ch][ut][0][nrow * 64 + kk] = hi;
        gWT[ch][ut][1][nrow * 64 + kk] = lo;
    }
}

// ---------------- main persistent kernel ----------------
__global__ void __launch_bounds__(NTH, 1) lstm_tc_kernel(
    const float* __restrict__ W_ih0,
    const float* __restrict__ b_ih0, const float* __restrict__ b_hh0,
    const float* __restrict__ b_ih1, const float* __restrict__ b_hh1,
    const float* __restrict__ fc_w,  const float* __restrict__ fc_b,
    float* __restrict__ out)
{
    extern __shared__ unsigned char sbuf[];

    __shared__ float sx[BM];
    __shared__ float sp[4][BM];
    __shared__ float sbias0[64], swih0[64], sbias1[64], sfcw16[16];

    const int tid = threadIdx.x;
    const int lid = tid & 31;
    const int wid = tid >> 5;
    const int wm  = wid & 3;          // M tile: rows wm*32..+31
    const int wn  = wid >> 2;         // N tile: gate-rows wn*16..+15 (units wn*4..+3)
    const int bt  = blockIdx.x >> 5;
    const int ut  = blockIdx.x & 31;
    const int b0  = bt * BM;
    const int u0  = ut * 16;
    const float fcb = fc_b[0];
    const uint32_t sb32 = smem_u32(sbuf);

    if (tid < 64) {
        const int lu = tid >> 2, g = tid & 3;
        const int j = g * HD + u0 + lu;
        sbias0[tid] = b_ih0[j] + b_hh0[j];
        swih0[tid]  = W_ih0[j];
        sbias1[tid] = b_ih1[j] + b_hh1[j];
    }
    if (tid < 16) sfcw16[tid] = fc_w[u0 + tid];
    __syncthreads();

    float acc[2][2][4];
    unsigned nbar = 0;

    // ---- stage chunk c into buffer bufsel (A: split h; B: pre-split weights)
    auto stage = [&](int c, int bufsel, int rp, int wp) {
        const __nv_bfloat16 *Ah, *Al; int k0;
        if (c < 8)       { Ah = &gH0h[rp][0][0]; Al = &gH0l[rp][0][0]; k0 = c * 64; }
        else if (c < 16) { Ah = &gH0h[wp][0][0]; Al = &gH0l[wp][0][0]; k0 = (c - 8) * 64; }
        else             { Ah = &gH1h[rp][0][0]; Al = &gH1l[rp][0][0]; k0 = (c - 16) * 64; }
        const uint32_t bb = sb32 + bufsel * BUFB;
        #pragma unroll
        for (int i = 0; i < 2; ++i) {
            const int s = tid + i * NTH;          // 1024 segs: 128 rows x 8
            const int row = s >> 3, seg = s & 7;
            const uint32_t d = bb + row * 144 + seg * 16;
            const size_t so = (size_t)(b0 + row) * HD + k0 + seg * 8;
            cpa16(d + OFF_AH, Ah + so);
            cpa16(d + OFF_AL, Al + so);
        }
        {
            const int s = tid;                    // 512 segs: 64 rows x 8
            const int row = s >> 3, seg = s & 7;
            const uint32_t d = bb + OFF_BH + row * 144 + seg * 16;
            const int eo = row * 64 + seg * 8;
            cpa16(d,                     &gWT[c][ut][0][eo]);
            cpa16(d + (OFF_BL - OFF_BH), &gWT[c][ut][1][eo]);
        }
        CP_COMMIT();
    };

    // ---- compute one K=64 chunk from buffer bufsel into acc
    auto compute = [&](int bufsel) {
        const uint32_t bb = sb32 + bufsel * BUFB;
        const uint32_t aoff = (wm * 32 + (lid & 15)) * 144 + (lid >> 4) * 16;
        const uint32_t boff = (wn * 16 + (lid & 15)) * 144 + (lid >> 4) * 16;
        #pragma unroll
        for (int ks = 0; ks < 4; ++ks) {
            const uint32_t ko = ks * 32;
            uint32_t Af[2][2][4];   // [split][mt][4]
            #pragma unroll
            for (int mt = 0; mt < 2; ++mt) {
                LDX4(Af[0][mt], bb + OFF_AH + aoff + mt * (16 * 144) + ko);
                LDX4(Af[1][mt], bb + OFF_AL + aoff + mt * (16 * 144) + ko);
            }
            uint32_t t0[4], t1[4];
            LDX4(t0, bb + OFF_BH + boff + ko);
            LDX4(t1, bb + OFF_BL + boff + ko);
            uint32_t Bf[2][2][2];   // [split][nt][2]
            Bf[0][0][0] = t0[0]; Bf[0][0][1] = t0[2];
            Bf[0][1][0] = t0[1]; Bf[0][1][1] = t0[3];
            Bf[1][0][0] = t1[0]; Bf[1][0][1] = t1[2];
            Bf[1][1][0] = t1[1]; Bf[1][1][1] = t1[3];
            #pragma unroll
            for (int mt = 0; mt < 2; ++mt)
                #pragma unroll
                for (int nt = 0; nt < 2; ++nt) {
                    MMA(acc[mt][nt], Af[0][mt], Bf[0][nt]);   // hi*hi
                    MMA(acc[mt][nt], Af[0][mt], Bf[1][nt]);   // hi*lo
                    MMA(acc[mt][nt], Af[1][mt], Bf[0][nt]);   // lo*hi
                }
        }
    };

    // ---- run chunks [ca,cb] with 2-deep cp.async pipeline
    auto run_layer = [&](int ca, int cb, int rp, int wp) {
        #pragma unroll
        for (int mt = 0; mt < 2; ++mt)
            #pragma unroll
            for (int nt = 0; nt < 2; ++nt)
                #pragma unroll
                for (int q = 0; q < 4; ++q) acc[mt][nt][q] = 0.0f;
        stage(ca, 0, rp, wp);
        int buf = 0;
        #pragma unroll 1
        for (int c = ca; c <= cb; ++c) {
            if (c < cb) {
                stage(c + 1, buf ^ 1, rp, wp);
                asm volatile("cp.async.wait_group 1;" ::: "memory");
            } else {
                asm volatile("cp.async.wait_group 0;" ::: "memory");
            }
            __syncthreads();
            compute(buf);
            __syncthreads();
            buf ^= 1;
        }
    };

    // ---- fused LSTM epilogue from register accumulators
    const int mbase = wm * 32 + (lid >> 2) + ((lid & 1) ? 8 : 0);
    const int lusub = wn * 4 + ((lid & 3) >> 1);

    auto epilogue = [&](bool L1, const float* sbias, float* Cbase,
                        __nv_bfloat16* Hhb, __nv_bfloat16* Hlb) {
        #pragma unroll
        for (int mt = 0; mt < 2; ++mt) {
            const int bl = mbase + mt * 16;
            const float xb = L1 ? 0.0f : sx[bl];
            float pb = 0.0f;
            #pragma unroll
            for (int nt = 0; nt < 2; ++nt) {
                float* d = acc[mt][nt];
                const float e0 = __shfl_xor_sync(0xFFFFFFFFu, d[0], 1);
                const float e1 = __shfl_xor_sync(0xFFFFFFFFu, d[1], 1);
                const float e2 = __shfl_xor_sync(0xFFFFFFFFu, d[2], 1);
                const float e3 = __shfl_xor_sync(0xFFFFFFFFu, d[3], 1);
                float gi, gf, gg, go;
                if (!(lid & 1)) { gi = d[0]; gf = d[1]; gg = e0; go = e1; }
                else            { gi = e2;  gf = e3;  gg = d[2]; go = d[3]; }
                const int lun = lusub + nt * 2;
                gi += sbias[4*lun+0]; gf += sbias[4*lun+1];
                gg += sbias[4*lun+2]; go += sbias[4*lun+3];
                if (!L1) {
                    gi += xb * swih0[4*lun+0]; gf += xb * swih0[4*lun+1];
                    gg += xb * swih0[4*lun+2]; go += xb * swih0[4*lun+3];
                }
                const size_t off = (size_t)(b0 + bl) * HD + u0 + lun;
                const float cold = Cbase[off];
                const float cn = sigf(gf) * cold + sigf(gi) * tanhfast(gg);
                const float hn = sigf(go) * tanhfast(cn);
                Cbase[off] = cn;
                const __nv_bfloat16 hh = __float2bfloat16(hn);
                Hhb[off] = hh;
                Hlb[off] = __float2bfloat16(hn - __bfloat162float(hh));
                if (L1) pb += hn * sfcw16[lun];
            }
            if (L1) {
                pb += __shfl_xor_sync(0xFFFFFFFFu, pb, 2);
                if (!(lid & 2)) sp[wn][bl] = pb;
            }
        }
    };

    #pragma unroll 1
    for (int t = 0; t < NSTEP; ++t) {
        const int rp = t & 1, wp = rp ^ 1;

        // ---- x_t from distributed fc partials
        if (t == 0) {
            if (tid < BM) sx[tid] = 0.0f;
        } else if (tid < BM) {
            float x = fcb;
            #pragma unroll
            for (int j = 0; j < NUT; ++j) x += __ldcg(&gXpart[j][b0 + tid]);
            sx[tid] = x;
            if (ut == 0) out[(size_t)(b0 + tid) * NSTEP + (t - 1)] = x;
        }

        // ---- layer 0: K=512 (chunks 0..7), fused update
        run_layer(0, 7, rp, wp);
        epilogue(false, sbias0, &gC0[0][0], &gH0h[wp][0][0], &gH0l[wp][0][0]);
        grid_sync(nbar);

        // ---- layer 1: K=1024 (chunks 8..23), fused update + fc partial
        run_layer(8, 23, rp, wp);
        epilogue(true, sbias1, &gC1[0][0], &gH1h[wp][0][0], &gH1l[wp][0][0]);
        __syncthreads();
        if (tid < BM) gXpart[ut][b0 + tid] = sp[0][tid] + sp[1][tid] + sp[2][tid] + sp[3][tid];
        grid_sync(nbar);
    }

    // ---- final prediction column 255
    if (ut == 0 && tid < BM) {
        float x = fcb;
        #pragma unroll
        for (int j = 0; j < NUT; ++j) x += __ldcg(&gXpart[j][b0 + tid]);
        out[(size_t)(b0 + tid) * NSTEP + 255] = x;
    }
}

extern "C" void kernel_launch(void* const* d_in, const int* in_sizes, int n_in,
                              void* d_out, int out_size)
{
    const float* h     = (const float*)d_in[0];
    const float* c     = (const float*)d_in[1];
    const float* W_ih0 = (const float*)d_in[2];
    const float* W_hh0 = (const float*)d_in[3];
    const float* b_ih0 = (const float*)d_in[4];
    const float* b_hh0 = (const float*)d_in[5];
    const float* W_ih1 = (const float*)d_in[6];
    const float* W_hh1 = (const float*)d_in[7];
    const float* b_ih1 = (const float*)d_in[8];
    const float* b_hh1 = (const float*)d_in[9];
    const float* fc_w  = (const float*)d_in[10];
    const float* fc_b  = (const float*)d_in[11];

    cudaFuncSetAttribute(lstm_tc_kernel, cudaFuncAttributeMaxDynamicSharedMemorySize, SMEM_DYN);

    init_kernel<<<1024, 256>>>(h, c, W_hh0, W_ih1, W_hh1);
    lstm_tc_kernel<<<NBLK, NTH, SMEM_DYN>>>(W_ih0, b_ih0, b_hh0, b_ih1, b_hh1,
                                            fc_w, fc_b, (float*)d_out);
}

// round 9
// speedup vs baseline: 2.7587x; 1.5887x over previous
#include <cuda_runtime.h>
#include <cuda_fp16.h>
#include <cstdint>

#define BSZ 512
#define HD 512
#define NSTEP 256
#define NUT 32
#define NBLK 128
#define GRPC 32          // CTAs per independent bt-group
#define BM 128
#define NTH 512
// smem ring: pitch 144B per 64-half row; A 128 rows, B 64 rows
#define OFF_B  18432
#define BUFB   27648
#define NBUF   4
#define SMEM_DYN (NBUF*BUFB)

// ---------------- persistent device state ----------------
__device__ __align__(16) __half gH0[2][BSZ][HD];
__device__ __align__(16) __half gH1[2][BSZ][HD];
__device__ __align__(16) float gC0[BSZ][HD];
__device__ __align__(16) float gC1[BSZ][HD];
__device__ float gXpart[NUT][BSZ];
__device__ unsigned gBarG[4];
// weights: 24 chunks x 32 u-tiles x (64 gate-rows x 64 k) fp16, k-contiguous
__device__ __align__(16) __half gWT[24][NUT][64*64];

// ---------------- helpers ----------------
__device__ __forceinline__ float sigf(float z)     { return 1.0f / (1.0f + __expf(-z)); }
__device__ __forceinline__ float tanhfast(float z) { return 2.0f / (1.0f + __expf(-2.0f * z)) - 1.0f; }

__device__ __forceinline__ uint32_t smem_u32(const void* p) {
    uint32_t a;
    asm("{ .reg .u64 t; cvta.to.shared.u64 t, %1; cvt.u32.u64 %0, t; }" : "=r"(a) : "l"(p));
    return a;
}
__device__ __forceinline__ void cpa16(uint32_t d, const void* s) {
    asm volatile("cp.async.cg.shared.global [%0], [%1], 16;"
                 :: "r"(d), "l"(__cvta_generic_to_global(s)) : "memory");
}
#define CP_COMMIT() asm volatile("cp.async.commit_group;" ::: "memory")

#define LDX4(r, a) \
    asm volatile("ldmatrix.sync.aligned.m8n8.x4.shared.b16 {%0,%1,%2,%3}, [%4];" \
        : "=r"((r)[0]), "=r"((r)[1]), "=r"((r)[2]), "=r"((r)[3]) : "r"(a))

#define MMA(d, a, b) \
    asm volatile("mma.sync.aligned.m16n8k16.row.col.f32.f16.f16.f32 " \
        "{%0,%1,%2,%3}, {%4,%5,%6,%7}, {%8,%9}, {%0,%1,%2,%3};" \
        : "+f"((d)[0]), "+f"((d)[1]), "+f"((d)[2]), "+f"((d)[3]) \
        : "r"((a)[0]), "r"((a)[1]), "r"((a)[2]), "r"((a)[3]), "r"((b)[0]), "r"((b)[1]))

// ---------------- init: states + fp16 weight transform ----------------
__global__ void init_kernel(const float* __restrict__ h, const float* __restrict__ c,
                            const float* __restrict__ W_hh0, const float* __restrict__ W_ih1,
                            const float* __restrict__ W_hh1)
{
    const int gtid = blockIdx.x * blockDim.x + threadIdx.x;
    const int gsz  = gridDim.x * blockDim.x;
    if (gtid < 4) gBarG[gtid] = 0u;

    const int n = BSZ * HD;
    for (int i = gtid; i < n; i += gsz) {
        (&gH0[0][0][0])[i] = __float2half(h[i]);
        (&gH1[0][0][0])[i] = __float2half(h[n + i]);
        (&gC0[0][0])[i] = c[i];
        (&gC1[0][0])[i] = c[n + i];
    }

    const long WN = 24L * NUT * 64 * 64;
    for (long idx = gtid; idx < WN; idx += gsz) {
        const int kk   = (int)(idx & 63);
        const int nrow = (int)((idx >> 6) & 63);
        const int ut   = (int)((idx >> 12) & 31);
        const int ch   = (int)(idx >> 17);
        const float* W = (ch < 8) ? W_hh0 : ((ch < 16) ? W_ih1 : W_hh1);
        // gate-row r -> weight row j: gate = r&3, unit = r>>2
        const int j = (nrow & 3) * HD + ut * 16 + (nrow >> 2);
        gWT[ch][ut][nrow * 64 + kk] = __float2half(W[(size_t)j * HD + (ch & 7) * 64 + kk]);
    }
}

// ---------------- main persistent kernel ----------------
__global__ void __launch_bounds__(NTH, 1) lstm_tc_kernel(
    const float* __restrict__ W_ih0,
    const float* __restrict__ b_ih0, const float* __restrict__ b_hh0,
    const float* __restrict__ b_ih1, const float* __restrict__ b_hh1,
    const float* __restrict__ fc_w,  const float* __restrict__ fc_b,
    float* __restrict__ out)
{
    extern __shared__ unsigned char sbuf[];

    __shared__ float sx[BM];
    __shared__ float sp[4][BM];
    __shared__ float sbias0[64], swih0[64], sbias1[64], sfcw16[16];

    const int tid = threadIdx.x;
    const int lid = tid & 31;
    const int wid = tid >> 5;
    const int wm  = wid & 3;          // M tile: rows wm*32..+31
    const int wn  = wid >> 2;         // N tile: gate-rows wn*16..+15 (units wn*4..+3)
    const int bt  = blockIdx.x >> 5;
    const int ut  = blockIdx.x & 31;
    const int b0  = bt * BM;
    const int u0  = ut * 16;
    const float fcb = fc_b[0];
    const uint32_t sb32 = smem_u32(sbuf);

    if (tid < 64) {
        const int lu = tid >> 2, g = tid & 3;
        const int j = g * HD + u0 + lu;
        sbias0[tid] = b_ih0[j] + b_hh0[j];
        swih0[tid]  = W_ih0[j];
        sbias1[tid] = b_ih1[j] + b_hh1[j];
    }
    if (tid < 16) sfcw16[tid] = fc_w[u0 + tid];
    __syncthreads();

    float acc[2][2][4];
    unsigned nbar = 0;

    // ---- group barrier over the 32 CTAs of this bt-group
    auto grid_sync = [&]() {
        __threadfence();
        __syncthreads();
        nbar++;
        if (tid == 0) {
            atomicAdd(&gBarG[bt], 1u);
            const unsigned target = nbar * GRPC;
            while (*((volatile unsigned*)&gBarG[bt]) < target) __nanosleep(64);
        }
        __syncthreads();
    };

    // ---- stage chunk c into ring buffer r (A: fp16 h; B: fp16 weights)
    auto stage = [&](int c, int r, int rp, int wp) {
        const __half* Ah; int k0;
        if (c < 8)       { Ah = &gH0[rp][0][0]; k0 = c * 64; }
        else if (c < 16) { Ah = &gH0[wp][0][0]; k0 = (c - 8) * 64; }
        else             { Ah = &gH1[rp][0][0]; k0 = (c - 16) * 64; }
        const uint32_t bb = sb32 + r * BUFB;
        {   // A: 1024 segs (128 rows x 8), 2 per thread
            #pragma unroll
            for (int i = 0; i < 2; ++i) {
                const int s = tid + i * NTH;
                const int row = s >> 3, seg = s & 7;
                cpa16(bb + row * 144 + seg * 16,
                      Ah + (size_t)(b0 + row) * HD + k0 + seg * 8);
            }
        }
        {   // B: 512 segs (64 rows x 8), 1 per thread
            const int row = tid >> 3, seg = tid & 7;
            cpa16(bb + OFF_B + row * 144 + seg * 16,
                  &gWT[c][ut][row * 64 + seg * 8]);
        }
        CP_COMMIT();
    };

    // ---- compute one K=64 chunk from ring buffer r into acc
    auto compute = [&](int r) {
        const uint32_t bb = sb32 + r * BUFB;
        const uint32_t aoff = (wm * 32 + (lid & 15)) * 144 + (lid >> 4) * 16;
        const uint32_t boff = OFF_B + (wn * 16 + (lid & 15)) * 144 + (lid >> 4) * 16;
        #pragma unroll
        for (int ks = 0; ks < 4; ++ks) {
            const uint32_t ko = ks * 32;
            uint32_t Af[2][4];
            LDX4(Af[0], bb + aoff + ko);
            LDX4(Af[1], bb + aoff + 16 * 144 + ko);
            uint32_t t0[4];
            LDX4(t0, bb + boff + ko);
            uint32_t Bf[2][2];
            Bf[0][0] = t0[0]; Bf[0][1] = t0[2];
            Bf[1][0] = t0[1]; Bf[1][1] = t0[3];
            #pragma unroll
            for (int mt = 0; mt < 2; ++mt)
                #pragma unroll
                for (int nt = 0; nt < 2; ++nt)
                    MMA(acc[mt][nt], Af[mt], Bf[nt]);
        }
    };

    // ---- run chunks [ca,cb]: 4-deep ring, stage 2 ahead, 1 sync/chunk
    auto run_layer = [&](int ca, int cb, int rp, int wp) {
        #pragma unroll
        for (int mt = 0; mt < 2; ++mt)
            #pragma unroll
            for (int nt = 0; nt < 2; ++nt)
                #pragma unroll
                for (int q = 0; q < 4; ++q) acc[mt][nt][q] = 0.0f;
        stage(ca, 0, rp, wp);
        if (ca + 1 <= cb) stage(ca + 1, 1, rp, wp);
        #pragma unroll 1
        for (int c = ca; c <= cb; ++c) {
            const int r = (c - ca) & (NBUF - 1);
            if (c + 2 <= cb) {
                stage(c + 2, (c + 2 - ca) & (NBUF - 1), rp, wp);
                asm volatile("cp.async.wait_group 2;" ::: "memory");
            } else if (c + 1 <= cb) {
                asm volatile("cp.async.wait_group 1;" ::: "memory");
            } else {
                asm volatile("cp.async.wait_group 0;" ::: "memory");
            }
            __syncthreads();
            compute(r);
        }
    };

    // ---- fused LSTM epilogue from register accumulators
    const int mbase = wm * 32 + (lid >> 2) + ((lid & 1) ? 8 : 0);
    const int lusub = wn * 4 + ((lid & 3) >> 1);

    auto epilogue = [&](bool L1, const float* sbias, float* Cbase, __half* Hb) {
        #pragma unroll
        for (int mt = 0; mt < 2; ++mt) {
            const int bl = mbase + mt * 16;
            const float xb = L1 ? 0.0f : sx[bl];
            float pb = 0.0f;
            #pragma unroll
            for (int nt = 0; nt < 2; ++nt) {
                float* d = acc[mt][nt];
                const float e0 = __shfl_xor_sync(0xFFFFFFFFu, d[0], 1);
                const float e1 = __shfl_xor_sync(0xFFFFFFFFu, d[1], 1);
                const float e2 = __shfl_xor_sync(0xFFFFFFFFu, d[2], 1);
                const float e3 = __shfl_xor_sync(0xFFFFFFFFu, d[3], 1);
                float gi, gf, gg, go;
                if (!(lid & 1)) { gi = d[0]; gf = d[1]; gg = e0; go = e1; }
                else            { gi = e2;  gf = e3;  gg = d[2]; go = d[3]; }
                const int lun = lusub + nt * 2;
                gi += sbias[4*lun+0]; gf += sbias[4*lun+1];
                gg += sbias[4*lun+2]; go += sbias[4*lun+3];
                if (!L1) {
                    gi += xb * swih0[4*lun+0]; gf += xb * swih0[4*lun+1];
                    gg += xb * swih0[4*lun+2]; go += xb * swih0[4*lun+3];
                }
                const size_t off = (size_t)(b0 + bl) * HD + u0 + lun;
                const float cold = Cbase[off];
                const float cn = sigf(gf) * cold + sigf(gi) * tanhfast(gg);
                const float hn = sigf(go) * tanhfast(cn);
                Cbase[off] = cn;
                Hb[off] = __float2half(hn);
                if (L1) pb += hn * sfcw16[lun];
            }
            if (L1) {
                pb += __shfl_xor_sync(0xFFFFFFFFu, pb, 2);
                if (!(lid & 2)) sp[wn][bl] = pb;
            }
        }
    };

    #pragma unroll 1
    for (int t = 0; t < NSTEP; ++t) {
        const int rp = t & 1, wp = rp ^ 1;

        // ---- x_t from distributed fc partials
        if (t == 0) {
            if (tid < BM) sx[tid] = 0.0f;
        } else if (tid < BM) {
            float x = fcb;
            #pragma unroll
            for (int j = 0; j < NUT; ++j) x += __ldcg(&gXpart[j][b0 + tid]);
            sx[tid] = x;
            if (ut == 0) out[(size_t)(b0 + tid) * NSTEP + (t - 1)] = x;
        }

        // ---- layer 0: K=512 (chunks 0..7), fused update
        run_layer(0, 7, rp, wp);
        epilogue(false, sbias0, &gC0[0][0], &gH0[wp][0][0]);
        grid_sync();

        // ---- layer 1: K=1024 (chunks 8..23), fused update + fc partial
        run_layer(8, 23, rp, wp);
        epilogue(true, sbias1, &gC1[0][0], &gH1[wp][0][0]);
        __syncthreads();
        if (tid < BM) gXpart[ut][b0 + tid] = sp[0][tid] + sp[1][tid] + sp[2][tid] + sp[3][tid];
        grid_sync();
    }

    // ---- final prediction column 255
    if (ut == 0 && tid < BM) {
        float x = fcb;
        #pragma unroll
        for (int j = 0; j < NUT; ++j) x += __ldcg(&gXpart[j][b0 + tid]);
        out[(size_t)(b0 + tid) * NSTEP + 255] = x;
    }
}

extern "C" void kernel_launch(void* const* d_in, const int* in_sizes, int n_in,
                              void* d_out, int out_size)
{
    const float* h     = (const float*)d_in[0];
    const float* c     = (const float*)d_in[1];
    const float* W_ih0 = (const float*)d_in[2];
    const float* W_hh0 = (const float*)d_in[3];
    const float* b_ih0 = (const float*)d_in[4];
    const float* b_hh0 = (const float*)d_in[5];
    const float* W_ih1 = (const float*)d_in[6];
    const float* W_hh1 = (const float*)d_in[7];
    const float* b_ih1 = (const float*)d_in[8];
    const float* b_hh1 = (const float*)d_in[9];
    const float* fc_w  = (const float*)d_in[10];
    const float* fc_b  = (const float*)d_in[11];

    cudaFuncSetAttribute(lstm_tc_kernel, cudaFuncAttributeMaxDynamicSharedMemorySize, SMEM_DYN);

    init_kernel<<<1024, 256>>>(h, c, W_hh0, W_ih1, W_hh1);
    lstm_tc_kernel<<<NBLK, NTH, SMEM_DYN>>>(W_ih0, b_ih0, b_hh0, b_ih1, b_hh1,
                                            fc_w, fc_b, (float*)d_out);
}